// round 1
// baseline (speedup 1.0000x reference)
#include <cuda_runtime.h>
#include <math.h>

// Biquad lowpass: fs=44100, fc=10000, Q=0.707.
// Pole magnitude = sqrt(a2) ~ 0.4203 -> impulse response decays 0.42^n.
// Truncate IIR to K-tap FIR: h_K ~ 0.42^24 ~ 1e-9 relative, far below 1e-3.
// Each thread computes 4 consecutive outputs from a 28-float register window
// (7x float4 global loads; L1 absorbs the inter-thread window overlap).

#define K_TAPS 24
#define WIN   (K_TAPS + 4)   // 28 floats = 7 float4
#define T_LEN 160000

struct FirParams {
    float h[K_TAPS];
};

__global__ __launch_bounds__(256) void lowpass_fir_kernel(
    const float* __restrict__ clip,
    float* __restrict__ out,
    FirParams p)
{
    const int t = (blockIdx.x * blockDim.x + threadIdx.x) * 4;
    if (t >= T_LEN) return;

    const size_t row = (size_t)blockIdx.y * T_LEN;
    const float* __restrict__ x = clip + row;

    float w[WIN];

    if (t >= K_TAPS) {
        // Fast path: fully in-bounds, 16B-aligned (t and row multiples of 4).
        const float4* __restrict__ p4 = reinterpret_cast<const float4*>(x + t - K_TAPS);
        #pragma unroll
        for (int i = 0; i < WIN / 4; i++) {
            float4 v = p4[i];
            w[4 * i + 0] = v.x;
            w[4 * i + 1] = v.y;
            w[4 * i + 2] = v.z;
            w[4 * i + 3] = v.w;
        }
    } else {
        // Left edge: zero-pad x[t'] for t' < 0.
        #pragma unroll
        for (int i = 0; i < WIN; i++) {
            int idx = t - K_TAPS + i;
            w[i] = (idx >= 0) ? x[idx] : 0.0f;
        }
    }

    float y0 = 0.f, y1 = 0.f, y2 = 0.f, y3 = 0.f;
    #pragma unroll
    for (int k = 0; k < K_TAPS; k++) {
        const float hk = p.h[k];
        // y_{t+j} = sum_k h_k * x[t+j-k];  w[i] = x[t - K + i]  ->  x[t+j-k] = w[K + j - k]
        y0 = fmaf(hk, w[K_TAPS + 0 - k], y0);
        y1 = fmaf(hk, w[K_TAPS + 1 - k], y1);
        y2 = fmaf(hk, w[K_TAPS + 2 - k], y2);
        y3 = fmaf(hk, w[K_TAPS + 3 - k], y3);
    }

    float4 r;
    r.x = y0; r.y = y1; r.z = y2; r.w = y3;
    *reinterpret_cast<float4*>(out + row + t) = r;
}

extern "C" void kernel_launch(void* const* d_in, const int* in_sizes, int n_in,
                              void* d_out, int out_size)
{
    const float* clip = (const float*)d_in[0];
    float* out = (float*)d_out;

    const int total = in_sizes[0];
    const int batch = total / T_LEN;   // 128

    // Coefficients in double, exactly as the reference computes them.
    const double fs = 44100.0, fc = 10000.0, q = 0.707;
    const double w0 = 2.0 * M_PI * fc / fs;
    const double alpha = sin(w0) / (2.0 * q);
    const double cw = cos(w0);
    const double a0 = 1.0 + alpha;
    const double b0 = ((1.0 - cw) / 2.0) / a0;
    const double b1 = (1.0 - cw) / a0;
    const double b2 = b0;
    const double a1 = (-2.0 * cw) / a0;
    const double a2 = (1.0 - alpha) / a0;

    // Impulse response of the biquad (truncated).
    double hd[K_TAPS];
    hd[0] = b0;
    hd[1] = b1 - a1 * hd[0];
    hd[2] = b2 - a1 * hd[1] - a2 * hd[0];
    for (int k = 3; k < K_TAPS; k++)
        hd[k] = -a1 * hd[k - 1] - a2 * hd[k - 2];

    FirParams p;
    for (int k = 0; k < K_TAPS; k++) p.h[k] = (float)hd[k];

    const int threads = 256;
    const int outs_per_block = threads * 4;                       // 1024
    const int blocks_x = (T_LEN + outs_per_block - 1) / outs_per_block;  // 157
    dim3 grid(blocks_x, batch);

    lowpass_fir_kernel<<<grid, threads>>>(clip, out, p);
}

// round 2
// speedup vs baseline: 1.2212x; 1.2212x over previous
#include <cuda_runtime.h>
#include <math.h>

// Biquad lowpass (fs=44100, fc=10000, Q=0.707) as a truncated-FIR convolution.
// Pole magnitude 0.4203 -> truncation error at K=16 taps ~ 0.4203^16 ~ 9.4e-7,
// far below the 1e-3 threshold.
// R2: 8 outputs/thread (24-float register window = 6x float4) to cut L1tex
// traffic from 7 to 3 loaded floats per output (L1 was the 73.6% bottleneck).

#define K_TAPS 16
#define OUTS   8
#define WIN    (K_TAPS + OUTS)  // 24 floats = 6 float4
#define T_LEN  160000

struct FirParams {
    float h[K_TAPS];
};

__global__ __launch_bounds__(256) void lowpass_fir_kernel(
    const float* __restrict__ clip,
    float* __restrict__ out,
    FirParams p)
{
    const int t = (blockIdx.x * blockDim.x + threadIdx.x) * OUTS;
    if (t >= T_LEN) return;

    const size_t row = (size_t)blockIdx.y * T_LEN;
    const float* __restrict__ x = clip + row;

    float w[WIN];

    if (t >= K_TAPS) {
        // Fast path: fully in-bounds, 16B-aligned (t multiple of 8, row mult of 4).
        const float4* __restrict__ p4 = reinterpret_cast<const float4*>(x + t - K_TAPS);
        #pragma unroll
        for (int i = 0; i < WIN / 4; i++) {
            float4 v = p4[i];
            w[4 * i + 0] = v.x;
            w[4 * i + 1] = v.y;
            w[4 * i + 2] = v.z;
            w[4 * i + 3] = v.w;
        }
    } else {
        // Left edge (first two threads of row): zero-pad x[t'] for t' < 0.
        #pragma unroll
        for (int i = 0; i < WIN; i++) {
            int idx = t - K_TAPS + i;
            w[i] = (idx >= 0) ? x[idx] : 0.0f;
        }
    }

    float y[OUTS];
    #pragma unroll
    for (int j = 0; j < OUTS; j++) y[j] = 0.0f;

    #pragma unroll
    for (int k = 0; k < K_TAPS; k++) {
        const float hk = p.h[k];
        // y_{t+j} = sum_k h_k * x[t+j-k]; w[i] = x[t - K + i] -> x[t+j-k] = w[K + j - k]
        #pragma unroll
        for (int j = 0; j < OUTS; j++)
            y[j] = fmaf(hk, w[K_TAPS + j - k], y[j]);
    }

    float4 r0, r1;
    r0.x = y[0]; r0.y = y[1]; r0.z = y[2]; r0.w = y[3];
    r1.x = y[4]; r1.y = y[5]; r1.z = y[6]; r1.w = y[7];
    float4* __restrict__ o4 = reinterpret_cast<float4*>(out + row + t);
    o4[0] = r0;
    o4[1] = r1;
}

extern "C" void kernel_launch(void* const* d_in, const int* in_sizes, int n_in,
                              void* d_out, int out_size)
{
    const float* clip = (const float*)d_in[0];
    float* out = (float*)d_out;

    const int total = in_sizes[0];
    const int batch = total / T_LEN;   // 128

    // Coefficients in double, exactly as the reference computes them.
    const double fs = 44100.0, fc = 10000.0, q = 0.707;
    const double w0 = 2.0 * M_PI * fc / fs;
    const double alpha = sin(w0) / (2.0 * q);
    const double cw = cos(w0);
    const double a0 = 1.0 + alpha;
    const double b0 = ((1.0 - cw) / 2.0) / a0;
    const double b1 = (1.0 - cw) / a0;
    const double b2 = b0;
    const double a1 = (-2.0 * cw) / a0;
    const double a2 = (1.0 - alpha) / a0;

    // Impulse response of the biquad (truncated to K_TAPS).
    double hd[K_TAPS];
    hd[0] = b0;
    hd[1] = b1 - a1 * hd[0];
    hd[2] = b2 - a1 * hd[1] - a2 * hd[0];
    for (int k = 3; k < K_TAPS; k++)
        hd[k] = -a1 * hd[k - 1] - a2 * hd[k - 2];

    FirParams p;
    for (int k = 0; k < K_TAPS; k++) p.h[k] = (float)hd[k];

    const int threads = 256;
    const int outs_per_block = threads * OUTS;                          // 2048
    const int blocks_x = (T_LEN + outs_per_block - 1) / outs_per_block; // 79
    dim3 grid(blocks_x, batch);

    lowpass_fir_kernel<<<grid, threads>>>(clip, out, p);
}